// round 7
// baseline (speedup 1.0000x reference)
#include <cuda_runtime.h>

// Adder2D: out[n,co,h,w] = -sum_{ci,kh,kw} |x_pad - w|
// Math per packed co-pair: FADD2 diff (fma) -> 64-bit sign-AND (2x LOP3, alu) -> FADD2 acc (fma).
// R7: occupancy push. CI_Q=4 (smem 12KB), launch_bounds(128,10) -> 10 blocks/SM (40 warps),
// div-free staging, full inner unroll, ci-split x16 with atomicAdd combine.

#define CI_   64
#define CO_   64
#define H_    32
#define W_    32

#define CO_T     8     // co per block -> 4 packed pairs
#define C2_      (CO_T/2)
#define TILE_H   8     // output rows per block (thread owns rows py, py+4)
#define CI_Q     4     // ci per block (reduction split x16)
#define THREADS  128

#define XS_ROWS (TILE_H + 2)   // 10
#define XS_COLS (W_ + 2)       // 34

typedef unsigned long long u64;

__device__ __forceinline__ u64 f2add(u64 a, u64 b) {
    u64 r;
    asm("add.rn.f32x2 %0, %1, %2;" : "=l"(r) : "l"(a), "l"(b));
    return r;
}

__device__ __forceinline__ u64 packff(float lo, float hi) {
    u64 r;
    asm("mov.b64 %0, {%1, %2};" : "=l"(r) : "f"(lo), "f"(hi));
    return r;
}

__device__ __forceinline__ float u64lo(u64 v) {
    return __uint_as_float((unsigned int)(v & 0xffffffffu));
}
__device__ __forceinline__ float u64hi(u64 v) {
    return __uint_as_float((unsigned int)(v >> 32));
}

__global__ void __launch_bounds__(THREADS, 10)
adder2d_kernel(const float* __restrict__ x,
               const float* __restrict__ w,
               float* __restrict__ out)
{
    // ci-slice x tile (halo incl.), each value duplicated in a u64: 10.9KB
    __shared__ u64 xs2[CI_Q][XS_ROWS][XS_COLS];
    // co-pair packed negated weights: 1.2KB
    __shared__ u64 ws2[C2_][CI_Q][9];

    const int tid = threadIdx.x;
    const int tx  = tid & 31;
    const int ty  = tid >> 5;
    const int h0  = blockIdx.x * TILE_H;
    const int co0 = blockIdx.y * CO_T;
    const int n   = blockIdx.z >> 4;
    const int ci0 = (blockIdx.z & 15) * CI_Q;

    // ---- stage w: negated + co-pair packed (144 entries) ----
    for (int i = tid; i < C2_ * CI_Q * 9; i += THREADS) {
        const int c2  = i / (CI_Q * 9);
        const int j   = i - c2 * (CI_Q * 9);
        const int cil = j / 9;
        const int tap = j - cil * 9;
        const float w0 = w[(co0 + 2 * c2 + 0) * (CI_ * 9) + (ci0 + cil) * 9 + tap];
        const float w1 = w[(co0 + 2 * c2 + 1) * (CI_ * 9) + (ci0 + cil) * 9 + tap];
        (&ws2[0][0][0])[i] = packff(-w0, -w1);
    }

    // ---- stage x slice (duplicated), exact-zero halo; div-free indexing ----
    const float* xn = x + (size_t)n * (CI_ * H_ * W_) + (size_t)ci0 * (H_ * W_);
    #pragma unroll
    for (int cl = 0; cl < CI_Q; ++cl) {
        const float* xc = xn + cl * (H_ * W_);
        for (int r = ty; r < XS_ROWS; r += 4) {
            const int gh = h0 + r - 1;
            const bool hok = (unsigned)gh < (unsigned)H_;
            for (int c = tx; c < XS_COLS; c += 32) {
                const int gw = c - 1;
                float v = 0.0f;
                if (hok && (unsigned)gw < (unsigned)W_)
                    v = xc[gh * W_ + gw];
                xs2[cl][r][c] = packff(v, v);
            }
        }
    }
    __syncthreads();

    // accumulators: [pixel(2)][co-pair(4)]
    u64 acc[2][C2_];
    #pragma unroll
    for (int p = 0; p < 2; ++p)
        #pragma unroll
        for (int c2 = 0; c2 < C2_; ++c2) acc[p][c2] = 0ull;

    const int px = tx;   // output column
    const int py = ty;   // owns rows py and py+4

    #pragma unroll
    for (int cl = 0; cl < CI_Q; ++cl) {
        #pragma unroll
        for (int kh = 0; kh < 3; ++kh) {
            #pragma unroll
            for (int kw = 0; kw < 3; ++kw) {
                const u64 x0 = xs2[cl][py + 0 + kh][px + kw];   // LDS.64
                const u64 x1 = xs2[cl][py + 4 + kh][px + kw];   // LDS.64
                const int tap = kh * 3 + kw;
                #pragma unroll
                for (int c2 = 0; c2 < C2_; ++c2) {
                    const u64 w2 = ws2[c2][cl][tap];            // LDS.64 (uniform bcast)
                    u64 d0 = f2add(x0, w2);                     // fma pipe
                    u64 d1 = f2add(x1, w2);
                    d0 &= 0x7fffffff7fffffffULL;                // alu pipe (2x LOP3)
                    d1 &= 0x7fffffff7fffffffULL;
                    acc[0][c2] = f2add(acc[0][c2], d0);          // fma pipe
                    acc[1][c2] = f2add(acc[1][c2], d1);
                }
            }
        }
    }

    // ---- epilogue: combine ci-slices via atomicAdd (out pre-zeroed) ----
    #pragma unroll
    for (int c2 = 0; c2 < C2_; ++c2) {
        #pragma unroll
        for (int p = 0; p < 2; ++p) {
            const float lo = u64lo(acc[p][c2]);
            const float hi = u64hi(acc[p][c2]);
            const int h = h0 + py + 4 * p;
            atomicAdd(&out[(((size_t)n * CO_ + (co0 + 2 * c2 + 0)) * H_ + h) * W_ + px], -lo);
            atomicAdd(&out[(((size_t)n * CO_ + (co0 + 2 * c2 + 1)) * H_ + h) * W_ + px], -hi);
        }
    }
}

extern "C" void kernel_launch(void* const* d_in, const int* in_sizes, int n_in,
                              void* d_out, int out_size)
{
    const float* x = (const float*)d_in[0];
    const float* w = (const float*)d_in[1];
    float* out = (float*)d_out;

    const int N = in_sizes[0] / (CI_ * H_ * W_);   // 16

    cudaMemsetAsync(d_out, 0, (size_t)out_size * sizeof(float));

    dim3 grid(H_ / TILE_H, CO_ / CO_T, N * 16);    // (4, 8, 256) = 8192 blocks
    adder2d_kernel<<<grid, THREADS>>>(x, w, out);
}